// round 6
// baseline (speedup 1.0000x reference)
#include <cuda_runtime.h>
#include <cstdint>

#define Bn   2
#define Tn   7
#define Hn   128
#define Wn   128
#define Pn   343            // 7*7*7 taps
#define Un   16
#define HW   (Hn*Wn)        // 16384
#define WT   16             // w-tile per block
#define RL   24             // padded patch row length (WT+6=22 -> 24)
#define CSTR (49*RL)        // channel stride in patch smem (floats)
#define ROWF (7*64*4)       // floats per ring row-slot: 7 taps x 64 thr x 4 w

// R6: stream filt via cp.async.cg (LDGSTS) into a 2-row smem ring.
// Rationale: R1-R5 showed DRAM% is pinned ~66% regardless of per-warp MLP or
// occupancy -> the LDG/L1tex in-flight tracking is the cap. cp.async bypasses
// it (L2 -> smem direct, deep async queue). Each thread copies exactly the
// 16B it later consumes, so wait_group alone orders it: no syncthreads in
// the main loop. Block = 64 thr = 16 u x 4 w-groups (float4), WT=16,
// 27.8KB smem -> 8 blocks/SM, grid 2048.
__global__ __launch_bounds__(64, 8)
void dynfilt_kernel(const float* __restrict__ x,
                    const float* __restrict__ filt,
                    float* __restrict__ out)
{
    __shared__ float sm[3 * CSTR];     // 14.1 KB patches
    __shared__ float ring[2 * ROWF];   // 14.3 KB filt ring (2 row slots)

    const int bx    = blockIdx.x;
    const int wq    = bx & 7;            // w eighth
    const int h     = (bx >> 3) & 127;   // row
    const int b     = bx >> 10;          // batch
    const int tid   = threadIdx.x;
    const int u     = tid >> 2;          // 0..15
    const int wg    = tid & 3;           // 0..3 -> w0 = 4*wg
    const int wbase = wq * WT;

    // ---- stage x patches: sm[(c*49 + t*7 + kh)*RL + j], j in [0,22), pad 0 ----
    for (int idx = tid; idx < 3 * 49 * RL; idx += 64) {
        int j   = idx % RL;
        int r   = idx / RL;          // c*49 + row
        int row = r % 49;            // t*7 + kh
        int c   = r / 49;
        int t   = row / 7;
        int kh  = row % 7;
        int gh  = h + kh - 3;
        int gw  = wbase + j - 3;
        float v = 0.f;
        if (j < WT + 6 && (unsigned)gh < (unsigned)Hn && (unsigned)gw < (unsigned)Wn)
            v = x[(((size_t)(b * 3 + c) * Tn + t) * Hn + gh) * Wn + gw];
        sm[idx] = v;
    }
    __syncthreads();

    // filt[b, p, u, h, w]; per-tap stride = Un*HW elems (1 MB).
    const size_t TAP = (size_t)Un * HW;
    const float* fp = filt + (((size_t)b * Pn) * Un + (size_t)u) * HW
                           + (size_t)h * Wn + wbase + 4 * wg;

    const uint32_t rbase = (uint32_t)__cvta_generic_to_shared(ring) + tid * 16;

    // prologue: async-load row 0 into slot 0
    #pragma unroll
    for (int kw = 0; kw < 7; ++kw)
        asm volatile("cp.async.cg.shared.global [%0], [%1], 16;\n"
                     :: "r"(rbase + kw * 1024), "l"(fp + (size_t)kw * TAP));
    asm volatile("cp.async.commit_group;\n");

    float acc[3][4] = {{0.f,0.f,0.f,0.f},{0.f,0.f,0.f,0.f},{0.f,0.f,0.f,0.f}};
    float ls[4]     = {0.f, 0.f, 0.f, 0.f};

    #pragma unroll 1
    for (int r = 0; r < 49; ++r) {
        const int s = r & 1;
        const float* fnext = fp + 7 * TAP;

        if (r < 48) {
            // issue next row into the other slot, then wait for current row
            const uint32_t nb = rbase + (s ^ 1) * (ROWF * 4);
            #pragma unroll
            for (int kw = 0; kw < 7; ++kw)
                asm volatile("cp.async.cg.shared.global [%0], [%1], 16;\n"
                             :: "r"(nb + kw * 1024), "l"(fnext + (size_t)kw * TAP));
            asm volatile("cp.async.commit_group;\n");
            asm volatile("cp.async.wait_group 1;\n");
        } else {
            asm volatile("cp.async.wait_group 0;\n");
        }

        // patch window [0..11] for 3 channels (uses [0..9])
        const float* srow = sm + r * RL + 4 * wg;
        float pw[3][12];
        #pragma unroll
        for (int c = 0; c < 3; ++c) {
            float4 q0 = *(const float4*)(srow + c * CSTR);
            float4 q1 = *(const float4*)(srow + c * CSTR + 4);
            float4 q2 = *(const float4*)(srow + c * CSTR + 8);
            pw[c][0] = q0.x; pw[c][1]  = q0.y; pw[c][2]  = q0.z; pw[c][3]  = q0.w;
            pw[c][4] = q1.x; pw[c][5]  = q1.y; pw[c][6]  = q1.z; pw[c][7]  = q1.w;
            pw[c][8] = q2.x; pw[c][9]  = q2.y; pw[c][10] = q2.z; pw[c][11] = q2.w;
        }

        // consume 7 taps of this row from the ring (own 16B per thread)
        const float* rr = ring + s * ROWF + tid * 4;
        #pragma unroll
        for (int kw = 0; kw < 7; ++kw) {
            float4 f = *(const float4*)(rr + kw * 256);
            float e0 = __expf(f.x);
            float e1 = __expf(f.y);
            float e2 = __expf(f.z);
            float e3 = __expf(f.w);
            ls[0] += e0; ls[1] += e1; ls[2] += e2; ls[3] += e3;
            #pragma unroll
            for (int c = 0; c < 3; ++c) {
                acc[c][0] += e0 * pw[c][kw];
                acc[c][1] += e1 * pw[c][kw + 1];
                acc[c][2] += e2 * pw[c][kw + 2];
                acc[c][3] += e3 * pw[c][kw + 3];
            }
        }

        fp = fnext;
    }

    // ---- epilogue: normalize + pixel shuffle ----
    // u -> (ur=u/4, uc=u%4); thread w's are wbase+4wg+i -> out col 4*w + uc.
    const int ur = u >> 2, uc = u & 3;
    const int Ho = Hn * 4, Wo = Wn * 4;
    const size_t cstride = (size_t)Ho * Wo;
    size_t obase = ((size_t)(b * 3) * Ho + (4 * h + ur)) * Wo
                 + (size_t)4 * (wbase + 4 * wg) + uc;

    #pragma unroll
    for (int i = 0; i < 4; ++i) {
        float inv = 1.f / ls[i];
        out[obase + 4 * i]               = acc[0][i] * inv;
        out[obase + 4 * i + cstride]     = acc[1][i] * inv;
        out[obase + 4 * i + 2 * cstride] = acc[2][i] * inv;
    }
}

extern "C" void kernel_launch(void* const* d_in, const int* in_sizes, int n_in,
                              void* d_out, int out_size)
{
    const float* x    = (const float*)d_in[0];   // [2,3,7,128,128]
    const float* filt = (const float*)d_in[1];   // [2,343,16,128,128]
    float* out        = (float*)d_out;           // [2,3,512,512]

    // Prefer max smem carveout so 8 blocks/SM (222.7 KB) actually fit.
    static bool configured = false;
    if (!configured) {
        cudaFuncSetAttribute(dynfilt_kernel,
                             cudaFuncAttributePreferredSharedMemoryCarveout, 100);
        configured = true;
    }

    // grid = B * H * (W/WT) = 2*128*8 = 2048 blocks, 64 threads each
    dynfilt_kernel<<<Bn * Hn * (Wn / WT), 64>>>(x, filt, out);
}

// round 7
// speedup vs baseline: 1.0300x; 1.0300x over previous
#include <cuda_runtime.h>
#include <cstdint>

#define Bn   2
#define Tn   7
#define Hn   128
#define Wn   128
#define Pn   343            // 7*7*7 taps
#define Un   16
#define HW   (Hn*Wn)        // 16384
#define WT   16             // w-tile per block
#define RL   24             // padded patch row length (WT+6=22 -> 24)
#define CSTR (49*RL)        // channel stride in patch smem (floats)
#define ROWF (7*64*4)       // floats per ring row-slot: 7 taps x 64 thr x 4 w

// R6: stream filt via cp.async.cg (LDGSTS) into a 2-row smem ring.
// Rationale: R1-R5 showed DRAM% is pinned ~66% regardless of per-warp MLP or
// occupancy -> the LDG/L1tex in-flight tracking is the cap. cp.async bypasses
// it (L2 -> smem direct, deep async queue). Each thread copies exactly the
// 16B it later consumes, so wait_group alone orders it: no syncthreads in
// the main loop. Block = 64 thr = 16 u x 4 w-groups (float4), WT=16,
// 27.8KB smem -> 8 blocks/SM, grid 2048.
__global__ __launch_bounds__(64, 8)
void dynfilt_kernel(const float* __restrict__ x,
                    const float* __restrict__ filt,
                    float* __restrict__ out)
{
    __shared__ float sm[3 * CSTR];     // 14.1 KB patches
    __shared__ float ring[2 * ROWF];   // 14.3 KB filt ring (2 row slots)

    const int bx    = blockIdx.x;
    const int wq    = bx & 7;            // w eighth
    const int h     = (bx >> 3) & 127;   // row
    const int b     = bx >> 10;          // batch
    const int tid   = threadIdx.x;
    const int u     = tid >> 2;          // 0..15
    const int wg    = tid & 3;           // 0..3 -> w0 = 4*wg
    const int wbase = wq * WT;

    // ---- stage x patches: sm[(c*49 + t*7 + kh)*RL + j], j in [0,22), pad 0 ----
    for (int idx = tid; idx < 3 * 49 * RL; idx += 64) {
        int j   = idx % RL;
        int r   = idx / RL;          // c*49 + row
        int row = r % 49;            // t*7 + kh
        int c   = r / 49;
        int t   = row / 7;
        int kh  = row % 7;
        int gh  = h + kh - 3;
        int gw  = wbase + j - 3;
        float v = 0.f;
        if (j < WT + 6 && (unsigned)gh < (unsigned)Hn && (unsigned)gw < (unsigned)Wn)
            v = x[(((size_t)(b * 3 + c) * Tn + t) * Hn + gh) * Wn + gw];
        sm[idx] = v;
    }
    __syncthreads();

    // filt[b, p, u, h, w]; per-tap stride = Un*HW elems (1 MB).
    const size_t TAP = (size_t)Un * HW;
    const float* fp = filt + (((size_t)b * Pn) * Un + (size_t)u) * HW
                           + (size_t)h * Wn + wbase + 4 * wg;

    const uint32_t rbase = (uint32_t)__cvta_generic_to_shared(ring) + tid * 16;

    // prologue: async-load row 0 into slot 0
    #pragma unroll
    for (int kw = 0; kw < 7; ++kw)
        asm volatile("cp.async.cg.shared.global [%0], [%1], 16;\n"
                     :: "r"(rbase + kw * 1024), "l"(fp + (size_t)kw * TAP));
    asm volatile("cp.async.commit_group;\n");

    float acc[3][4] = {{0.f,0.f,0.f,0.f},{0.f,0.f,0.f,0.f},{0.f,0.f,0.f,0.f}};
    float ls[4]     = {0.f, 0.f, 0.f, 0.f};

    #pragma unroll 1
    for (int r = 0; r < 49; ++r) {
        const int s = r & 1;
        const float* fnext = fp + 7 * TAP;

        if (r < 48) {
            // issue next row into the other slot, then wait for current row
            const uint32_t nb = rbase + (s ^ 1) * (ROWF * 4);
            #pragma unroll
            for (int kw = 0; kw < 7; ++kw)
                asm volatile("cp.async.cg.shared.global [%0], [%1], 16;\n"
                             :: "r"(nb + kw * 1024), "l"(fnext + (size_t)kw * TAP));
            asm volatile("cp.async.commit_group;\n");
            asm volatile("cp.async.wait_group 1;\n");
        } else {
            asm volatile("cp.async.wait_group 0;\n");
        }

        // patch window [0..11] for 3 channels (uses [0..9])
        const float* srow = sm + r * RL + 4 * wg;
        float pw[3][12];
        #pragma unroll
        for (int c = 0; c < 3; ++c) {
            float4 q0 = *(const float4*)(srow + c * CSTR);
            float4 q1 = *(const float4*)(srow + c * CSTR + 4);
            float4 q2 = *(const float4*)(srow + c * CSTR + 8);
            pw[c][0] = q0.x; pw[c][1]  = q0.y; pw[c][2]  = q0.z; pw[c][3]  = q0.w;
            pw[c][4] = q1.x; pw[c][5]  = q1.y; pw[c][6]  = q1.z; pw[c][7]  = q1.w;
            pw[c][8] = q2.x; pw[c][9]  = q2.y; pw[c][10] = q2.z; pw[c][11] = q2.w;
        }

        // consume 7 taps of this row from the ring (own 16B per thread)
        const float* rr = ring + s * ROWF + tid * 4;
        #pragma unroll
        for (int kw = 0; kw < 7; ++kw) {
            float4 f = *(const float4*)(rr + kw * 256);
            float e0 = __expf(f.x);
            float e1 = __expf(f.y);
            float e2 = __expf(f.z);
            float e3 = __expf(f.w);
            ls[0] += e0; ls[1] += e1; ls[2] += e2; ls[3] += e3;
            #pragma unroll
            for (int c = 0; c < 3; ++c) {
                acc[c][0] += e0 * pw[c][kw];
                acc[c][1] += e1 * pw[c][kw + 1];
                acc[c][2] += e2 * pw[c][kw + 2];
                acc[c][3] += e3 * pw[c][kw + 3];
            }
        }

        fp = fnext;
    }

    // ---- epilogue: normalize + pixel shuffle ----
    // u -> (ur=u/4, uc=u%4); thread w's are wbase+4wg+i -> out col 4*w + uc.
    const int ur = u >> 2, uc = u & 3;
    const int Ho = Hn * 4, Wo = Wn * 4;
    const size_t cstride = (size_t)Ho * Wo;
    size_t obase = ((size_t)(b * 3) * Ho + (4 * h + ur)) * Wo
                 + (size_t)4 * (wbase + 4 * wg) + uc;

    #pragma unroll
    for (int i = 0; i < 4; ++i) {
        float inv = 1.f / ls[i];
        out[obase + 4 * i]               = acc[0][i] * inv;
        out[obase + 4 * i + cstride]     = acc[1][i] * inv;
        out[obase + 4 * i + 2 * cstride] = acc[2][i] * inv;
    }
}

extern "C" void kernel_launch(void* const* d_in, const int* in_sizes, int n_in,
                              void* d_out, int out_size)
{
    const float* x    = (const float*)d_in[0];   // [2,3,7,128,128]
    const float* filt = (const float*)d_in[1];   // [2,343,16,128,128]
    float* out        = (float*)d_out;           // [2,3,512,512]

    // Prefer max smem carveout so 8 blocks/SM (222.7 KB) actually fit.
    static bool configured = false;
    if (!configured) {
        cudaFuncSetAttribute(dynfilt_kernel,
                             cudaFuncAttributePreferredSharedMemoryCarveout, 100);
        configured = true;
    }

    // grid = B * H * (W/WT) = 2*128*8 = 2048 blocks, 64 threads each
    dynfilt_kernel<<<Bn * Hn * (Wn / WT), 64>>>(x, filt, out);
}

// round 8
// speedup vs baseline: 1.0410x; 1.0107x over previous
#include <cuda_runtime.h>
#include <cstdint>

#define Bn   2
#define Tn   7
#define Hn   128
#define Wn   128
#define Pn   343            // 7*7*7 taps
#define Un   16
#define HW   (Hn*Wn)        // 16384
#define WT   16             // w-tile per block
#define RL   24             // padded patch row length (WT+6=22 -> 24)
#define CSTR (49*RL)        // channel stride in patch smem (floats)
#define ROWF (7*64*4)       // floats per ring row-slot: 7 taps x 64 thr x 4 w

// R6: stream filt via cp.async.cg (LDGSTS) into a 2-row smem ring.
// Rationale: R1-R5 showed DRAM% is pinned ~66% regardless of per-warp MLP or
// occupancy -> the LDG/L1tex in-flight tracking is the cap. cp.async bypasses
// it (L2 -> smem direct, deep async queue). Each thread copies exactly the
// 16B it later consumes, so wait_group alone orders it: no syncthreads in
// the main loop. Block = 64 thr = 16 u x 4 w-groups (float4), WT=16,
// 27.8KB smem -> 8 blocks/SM, grid 2048.
__global__ __launch_bounds__(64, 8)
void dynfilt_kernel(const float* __restrict__ x,
                    const float* __restrict__ filt,
                    float* __restrict__ out)
{
    __shared__ float sm[3 * CSTR];     // 14.1 KB patches
    __shared__ float ring[2 * ROWF];   // 14.3 KB filt ring (2 row slots)

    const int bx    = blockIdx.x;
    const int wq    = bx & 7;            // w eighth
    const int h     = (bx >> 3) & 127;   // row
    const int b     = bx >> 10;          // batch
    const int tid   = threadIdx.x;
    const int u     = tid >> 2;          // 0..15
    const int wg    = tid & 3;           // 0..3 -> w0 = 4*wg
    const int wbase = wq * WT;

    // ---- stage x patches: sm[(c*49 + t*7 + kh)*RL + j], j in [0,22), pad 0 ----
    for (int idx = tid; idx < 3 * 49 * RL; idx += 64) {
        int j   = idx % RL;
        int r   = idx / RL;          // c*49 + row
        int row = r % 49;            // t*7 + kh
        int c   = r / 49;
        int t   = row / 7;
        int kh  = row % 7;
        int gh  = h + kh - 3;
        int gw  = wbase + j - 3;
        float v = 0.f;
        if (j < WT + 6 && (unsigned)gh < (unsigned)Hn && (unsigned)gw < (unsigned)Wn)
            v = x[(((size_t)(b * 3 + c) * Tn + t) * Hn + gh) * Wn + gw];
        sm[idx] = v;
    }
    __syncthreads();

    // filt[b, p, u, h, w]; per-tap stride = Un*HW elems (1 MB).
    const size_t TAP = (size_t)Un * HW;
    const float* fp = filt + (((size_t)b * Pn) * Un + (size_t)u) * HW
                           + (size_t)h * Wn + wbase + 4 * wg;

    const uint32_t rbase = (uint32_t)__cvta_generic_to_shared(ring) + tid * 16;

    // prologue: async-load row 0 into slot 0
    #pragma unroll
    for (int kw = 0; kw < 7; ++kw)
        asm volatile("cp.async.cg.shared.global [%0], [%1], 16;\n"
                     :: "r"(rbase + kw * 1024), "l"(fp + (size_t)kw * TAP));
    asm volatile("cp.async.commit_group;\n");

    float acc[3][4] = {{0.f,0.f,0.f,0.f},{0.f,0.f,0.f,0.f},{0.f,0.f,0.f,0.f}};
    float ls[4]     = {0.f, 0.f, 0.f, 0.f};

    #pragma unroll 1
    for (int r = 0; r < 49; ++r) {
        const int s = r & 1;
        const float* fnext = fp + 7 * TAP;

        if (r < 48) {
            // issue next row into the other slot, then wait for current row
            const uint32_t nb = rbase + (s ^ 1) * (ROWF * 4);
            #pragma unroll
            for (int kw = 0; kw < 7; ++kw)
                asm volatile("cp.async.cg.shared.global [%0], [%1], 16;\n"
                             :: "r"(nb + kw * 1024), "l"(fnext + (size_t)kw * TAP));
            asm volatile("cp.async.commit_group;\n");
            asm volatile("cp.async.wait_group 1;\n");
        } else {
            asm volatile("cp.async.wait_group 0;\n");
        }

        // patch window [0..11] for 3 channels (uses [0..9])
        const float* srow = sm + r * RL + 4 * wg;
        float pw[3][12];
        #pragma unroll
        for (int c = 0; c < 3; ++c) {
            float4 q0 = *(const float4*)(srow + c * CSTR);
            float4 q1 = *(const float4*)(srow + c * CSTR + 4);
            float4 q2 = *(const float4*)(srow + c * CSTR + 8);
            pw[c][0] = q0.x; pw[c][1]  = q0.y; pw[c][2]  = q0.z; pw[c][3]  = q0.w;
            pw[c][4] = q1.x; pw[c][5]  = q1.y; pw[c][6]  = q1.z; pw[c][7]  = q1.w;
            pw[c][8] = q2.x; pw[c][9]  = q2.y; pw[c][10] = q2.z; pw[c][11] = q2.w;
        }

        // consume 7 taps of this row from the ring (own 16B per thread)
        const float* rr = ring + s * ROWF + tid * 4;
        #pragma unroll
        for (int kw = 0; kw < 7; ++kw) {
            float4 f = *(const float4*)(rr + kw * 256);
            float e0 = __expf(f.x);
            float e1 = __expf(f.y);
            float e2 = __expf(f.z);
            float e3 = __expf(f.w);
            ls[0] += e0; ls[1] += e1; ls[2] += e2; ls[3] += e3;
            #pragma unroll
            for (int c = 0; c < 3; ++c) {
                acc[c][0] += e0 * pw[c][kw];
                acc[c][1] += e1 * pw[c][kw + 1];
                acc[c][2] += e2 * pw[c][kw + 2];
                acc[c][3] += e3 * pw[c][kw + 3];
            }
        }

        fp = fnext;
    }

    // ---- epilogue: normalize + pixel shuffle ----
    // u -> (ur=u/4, uc=u%4); thread w's are wbase+4wg+i -> out col 4*w + uc.
    const int ur = u >> 2, uc = u & 3;
    const int Ho = Hn * 4, Wo = Wn * 4;
    const size_t cstride = (size_t)Ho * Wo;
    size_t obase = ((size_t)(b * 3) * Ho + (4 * h + ur)) * Wo
                 + (size_t)4 * (wbase + 4 * wg) + uc;

    #pragma unroll
    for (int i = 0; i < 4; ++i) {
        float inv = 1.f / ls[i];
        out[obase + 4 * i]               = acc[0][i] * inv;
        out[obase + 4 * i + cstride]     = acc[1][i] * inv;
        out[obase + 4 * i + 2 * cstride] = acc[2][i] * inv;
    }
}

extern "C" void kernel_launch(void* const* d_in, const int* in_sizes, int n_in,
                              void* d_out, int out_size)
{
    const float* x    = (const float*)d_in[0];   // [2,3,7,128,128]
    const float* filt = (const float*)d_in[1];   // [2,343,16,128,128]
    float* out        = (float*)d_out;           // [2,3,512,512]

    // Prefer max smem carveout so 8 blocks/SM (222.7 KB) actually fit.
    static bool configured = false;
    if (!configured) {
        cudaFuncSetAttribute(dynfilt_kernel,
                             cudaFuncAttributePreferredSharedMemoryCarveout, 100);
        configured = true;
    }

    // grid = B * H * (W/WT) = 2*128*8 = 2048 blocks, 64 threads each
    dynfilt_kernel<<<Bn * Hn * (Wn / WT), 64>>>(x, filt, out);
}

// round 9
// speedup vs baseline: 1.0418x; 1.0009x over previous
#include <cuda_runtime.h>
#include <cstdint>

#define Bn    2
#define Tn    7
#define Hn    128
#define Wn    128
#define Pn    343           // 7*7*7 taps
#define Un    16
#define HW    (Hn*Wn)       // 16384
#define WT    16            // w-tile per block
#define RL    24            // padded patch row length (WT+6=22 -> 24)
#define CSTR  (49*RL)       // channel stride in patch smem (floats)
#define DEPTH 8             // cp.async pipeline depth in taps
#define NT    64            // threads per block
#define SLOTF (NT*4)        // floats per ring slot (64 thr x 4 w)

// R9: cp.async, tap-granularity pipeline depth 8, 10 blocks/SM.
// R6 showed cp.async delivers MORE DRAM per warp than LDG (3.9 vs 2.9 %/warp)
// but was capped at 16 warps/SM by 28KB smem + row-granular wait_group 1.
// Here: ring slot = ONE tap (1KB), steady wait_group 7 -> 8 taps always in
// flight per thread; smem 22.3KB -> 10 blocks/SM; no syncthreads in loop
// (each thread consumes only its own 16B).
__global__ __launch_bounds__(NT, 10)
void dynfilt_kernel(const float* __restrict__ x,
                    const float* __restrict__ filt,
                    float* __restrict__ out)
{
    __shared__ float sm[3 * CSTR];        // 14.1 KB patches
    __shared__ float ring[DEPTH * SLOTF]; // 8 KB filt ring

    const int bx    = blockIdx.x;
    const int wq    = bx & 7;            // w eighth
    const int h     = (bx >> 3) & 127;   // row
    const int b     = bx >> 10;          // batch
    const int tid   = threadIdx.x;
    const int u     = tid >> 2;          // 0..15
    const int wg    = tid & 3;           // 0..3 -> w0 = 4*wg
    const int wbase = wq * WT;

    // ---- stage x patches: sm[(c*49 + t*7 + kh)*RL + j], j in [0,22), pad 0 ----
    for (int idx = tid; idx < 3 * 49 * RL; idx += NT) {
        int j   = idx % RL;
        int r   = idx / RL;          // c*49 + row
        int row = r % 49;            // t*7 + kh
        int c   = r / 49;
        int t   = row / 7;
        int kh  = row % 7;
        int gh  = h + kh - 3;
        int gw  = wbase + j - 3;
        float v = 0.f;
        if (j < WT + 6 && (unsigned)gh < (unsigned)Hn && (unsigned)gw < (unsigned)Wn)
            v = x[(((size_t)(b * 3 + c) * Tn + t) * Hn + gh) * Wn + gw];
        sm[idx] = v;
    }
    __syncthreads();

    // filt[b, p, u, h, w]; per-tap stride = Un*HW elems (1 MB).
    const size_t TAP = (size_t)Un * HW;
    const float* fpAhead = filt + (((size_t)b * Pn) * Un + (size_t)u) * HW
                                + (size_t)h * Wn + wbase + 4 * wg;

    const uint32_t rbase = (uint32_t)__cvta_generic_to_shared(ring) + tid * 16;

    // prologue: fill the pipeline with taps 0..DEPTH-1 (one commit per tap)
    #pragma unroll
    for (int qq = 0; qq < DEPTH; ++qq) {
        asm volatile("cp.async.cg.shared.global [%0], [%1], 16;\n"
                     :: "r"(rbase + qq * (SLOTF * 4)), "l"(fpAhead));
        asm volatile("cp.async.commit_group;\n");
        fpAhead += TAP;
    }

    float acc[3][4] = {{0.f,0.f,0.f,0.f},{0.f,0.f,0.f,0.f},{0.f,0.f,0.f,0.f}};
    float ls[4]     = {0.f, 0.f, 0.f, 0.f};

    int sbase = 0;   // slot index of tap r*7 (mod 8)

    // ---- main: rows 0..47 (taps 0..335), tail row 48 handled after ----
    #pragma unroll 1
    for (int r = 0; r < 48; ++r) {
        // patch window [0..11] for 3 channels
        const float* srow = sm + r * RL + 4 * wg;
        float pw[3][12];
        #pragma unroll
        for (int c = 0; c < 3; ++c) {
            float4 q0 = *(const float4*)(srow + c * CSTR);
            float4 q1 = *(const float4*)(srow + c * CSTR + 4);
            float4 q2 = *(const float4*)(srow + c * CSTR + 8);
            pw[c][0] = q0.x; pw[c][1]  = q0.y; pw[c][2]  = q0.z; pw[c][3]  = q0.w;
            pw[c][4] = q1.x; pw[c][5]  = q1.y; pw[c][6]  = q1.z; pw[c][7]  = q1.w;
            pw[c][8] = q2.x; pw[c][9]  = q2.y; pw[c][10] = q2.z; pw[c][11] = q2.w;
        }

        #pragma unroll
        for (int kw = 0; kw < 7; ++kw) {
            // tap q = 7r+kw is complete once <= DEPTH-1 groups are pending
            asm volatile("cp.async.wait_group %0;\n" :: "n"(DEPTH - 1));

            const int slot = (sbase + kw) & (DEPTH - 1);
            float4 f = *(const float4*)(ring + slot * SLOTF + tid * 4);

            float e0 = __expf(f.x);
            float e1 = __expf(f.y);
            float e2 = __expf(f.z);
            float e3 = __expf(f.w);
            ls[0] += e0; ls[1] += e1; ls[2] += e2; ls[3] += e3;
            #pragma unroll
            for (int c = 0; c < 3; ++c) {
                acc[c][0] += e0 * pw[c][kw];
                acc[c][1] += e1 * pw[c][kw + 1];
                acc[c][2] += e2 * pw[c][kw + 2];
                acc[c][3] += e3 * pw[c][kw + 3];
            }

            // refill this slot with tap q+DEPTH (q+8 <= 343 always here;
            // q=335 -> issues tap 343? no: q max in main = 7*47+6 = 335,
            // q+8 = 343 out of range guard below)
            if (r * 7 + kw + DEPTH < Pn) {
                asm volatile("cp.async.cg.shared.global [%0], [%1], 16;\n"
                             :: "r"(rbase + slot * (SLOTF * 4)), "l"(fpAhead));
                fpAhead += TAP;
            }
            asm volatile("cp.async.commit_group;\n");
        }
        sbase = (sbase + 7) & (DEPTH - 1);
    }

    // ---- tail row 48: taps 336..342 all committed; drain everything ----
    {
        asm volatile("cp.async.wait_group 0;\n");
        const float* srow = sm + 48 * RL + 4 * wg;
        float pw[3][12];
        #pragma unroll
        for (int c = 0; c < 3; ++c) {
            float4 q0 = *(const float4*)(srow + c * CSTR);
            float4 q1 = *(const float4*)(srow + c * CSTR + 4);
            float4 q2 = *(const float4*)(srow + c * CSTR + 8);
            pw[c][0] = q0.x; pw[c][1]  = q0.y; pw[c][2]  = q0.z; pw[c][3]  = q0.w;
            pw[c][4] = q1.x; pw[c][5]  = q1.y; pw[c][6]  = q1.z; pw[c][7]  = q1.w;
            pw[c][8] = q2.x; pw[c][9]  = q2.y; pw[c][10] = q2.z; pw[c][11] = q2.w;
        }
        #pragma unroll
        for (int kw = 0; kw < 7; ++kw) {
            const int slot = (sbase + kw) & (DEPTH - 1);
            float4 f = *(const float4*)(ring + slot * SLOTF + tid * 4);
            float e0 = __expf(f.x);
            float e1 = __expf(f.y);
            float e2 = __expf(f.z);
            float e3 = __expf(f.w);
            ls[0] += e0; ls[1] += e1; ls[2] += e2; ls[3] += e3;
            #pragma unroll
            for (int c = 0; c < 3; ++c) {
                acc[c][0] += e0 * pw[c][kw];
                acc[c][1] += e1 * pw[c][kw + 1];
                acc[c][2] += e2 * pw[c][kw + 2];
                acc[c][3] += e3 * pw[c][kw + 3];
            }
        }
    }

    // ---- epilogue: normalize + pixel shuffle ----
    // u -> (ur=u/4, uc=u%4); thread w's are wbase+4wg+i -> out col 4*w + uc.
    const int ur = u >> 2, uc = u & 3;
    const int Ho = Hn * 4, Wo = Wn * 4;
    const size_t cstride = (size_t)Ho * Wo;
    size_t obase = ((size_t)(b * 3) * Ho + (4 * h + ur)) * Wo
                 + (size_t)4 * (wbase + 4 * wg) + uc;

    #pragma unroll
    for (int i = 0; i < 4; ++i) {
        float inv = 1.f / ls[i];
        out[obase + 4 * i]               = acc[0][i] * inv;
        out[obase + 4 * i + cstride]     = acc[1][i] * inv;
        out[obase + 4 * i + 2 * cstride] = acc[2][i] * inv;
    }
}

extern "C" void kernel_launch(void* const* d_in, const int* in_sizes, int n_in,
                              void* d_out, int out_size)
{
    const float* x    = (const float*)d_in[0];   // [2,3,7,128,128]
    const float* filt = (const float*)d_in[1];   // [2,343,16,128,128]
    float* out        = (float*)d_out;           // [2,3,512,512]

    static bool configured = false;
    if (!configured) {
        cudaFuncSetAttribute(dynfilt_kernel,
                             cudaFuncAttributePreferredSharedMemoryCarveout, 100);
        configured = true;
    }

    // grid = B * H * (W/WT) = 2*128*8 = 2048 blocks, 64 threads each
    dynfilt_kernel<<<Bn * Hn * (Wn / WT), NT>>>(x, filt, out);
}